// round 4
// baseline (speedup 1.0000x reference)
#include <cuda_runtime.h>
#include <math.h>

#define B_    2
#define L_    2048
#define DIM_  1024
#define NH    16
#define NKV   4
#define HD    64
#define KVD   (NKV*HD)      // 256
#define NTOK  (B_*L_)       // 4096

// Scratch (no cudaMalloc allowed)
__device__ float g_q[NTOK*DIM_];     // 16 MB
__device__ float g_k[NTOK*KVD];      // 4 MB
__device__ float g_v[NTOK*KVD];      // 4 MB
__device__ float g_ao[NTOK*DIM_];    // 16 MB

// ---------------------------------------------------------------------------
// Tiled fp32 GEMM: C[M,N] = A[M,K] @ B[K,N], all row-major.
// 64x64 tile, BK=16, 256 threads, 4x4 per thread. Assumes M,N % 64 == 0, K % 16 == 0.
// ---------------------------------------------------------------------------
__global__ __launch_bounds__(256) void sgemm64(const float* __restrict__ A,
                                               const float* __restrict__ B,
                                               float* __restrict__ C,
                                               int M, int N, int K) {
    __shared__ float As[16][68];   // transposed A tile: As[k][m]
    __shared__ float Bs[16][68];   // Bs[k][n]

    const int tid = threadIdx.x;
    const int tx  = tid & 15;          // N sub-tile
    const int ty  = tid >> 4;          // M sub-tile
    const int m0  = blockIdx.y * 64;
    const int n0  = blockIdx.x * 64;

    // load mapping
    const int ar = tid >> 2;           // 0..63  (A tile row)
    const int ac = (tid & 3) * 4;      // 0,4,8,12 (A tile col, float4)
    const int br = tid >> 4;           // 0..15  (B tile row)
    const int bc = (tid & 15) * 4;     // 0..60  (B tile col, float4)

    float acc[4][4] = {};

    for (int k0 = 0; k0 < K; k0 += 16) {
        float4 a4 = *(const float4*)&A[(size_t)(m0 + ar) * K + k0 + ac];
        As[ac + 0][ar] = a4.x;
        As[ac + 1][ar] = a4.y;
        As[ac + 2][ar] = a4.z;
        As[ac + 3][ar] = a4.w;
        *(float4*)&Bs[br][bc] = *(const float4*)&B[(size_t)(k0 + br) * N + n0 + bc];
        __syncthreads();

        #pragma unroll
        for (int kk = 0; kk < 16; kk++) {
            float4 av = *(const float4*)&As[kk][ty * 4];
            float4 bv = *(const float4*)&Bs[kk][tx * 4];
            float ra[4] = {av.x, av.y, av.z, av.w};
            float rb[4] = {bv.x, bv.y, bv.z, bv.w};
            #pragma unroll
            for (int i = 0; i < 4; i++)
                #pragma unroll
                for (int j = 0; j < 4; j++)
                    acc[i][j] += ra[i] * rb[j];
        }
        __syncthreads();
    }

    #pragma unroll
    for (int i = 0; i < 4; i++) {
        float4 out = make_float4(acc[i][0], acc[i][1], acc[i][2], acc[i][3]);
        *(float4*)&C[(size_t)(m0 + ty * 4 + i) * N + n0 + tx * 4] = out;
    }
}

// ---------------------------------------------------------------------------
// Fused per-head RMSNorm + RoPE, applied in-place to g_q and g_k.
// One warp per head-row (64 elems -> float2 per lane).
// ---------------------------------------------------------------------------
__global__ __launch_bounds__(256) void rmsrope_kernel(const float* __restrict__ gq,
                                                      const float* __restrict__ gk) {
    const int gw   = blockIdx.x * 8 + (threadIdx.x >> 5);
    const int lane = threadIdx.x & 31;

    float* row;
    const float* g;
    int tok;
    if (gw < NTOK * NH) {
        tok = gw >> 4;
        int h = gw & 15;
        row = g_q + (size_t)tok * DIM_ + h * HD;
        g   = gq;
    } else {
        int r = gw - NTOK * NH;
        tok = r >> 2;
        int hk = r & 3;
        row = g_k + (size_t)tok * KVD + hk * HD;
        g   = gk;
    }
    const int pos = tok & (L_ - 1);

    float2 v = ((const float2*)row)[lane];
    float ss = v.x * v.x + v.y * v.y;
    #pragma unroll
    for (int off = 16; off > 0; off >>= 1)
        ss += __shfl_xor_sync(0xffffffffu, ss, off);
    float rn = rsqrtf(ss * (1.0f / 64.0f) + 1e-6f);

    float2 gg = ((const float2*)g)[lane];
    float t1 = v.x * rn * gg.x;
    float t2 = v.y * rn * gg.y;

    // inv_freq = 10000^(-p/32), p = lane
    float inv_freq = exp2f((float)lane * (-13.287712379549449f / 32.0f));
    float ang = (float)pos * inv_freq;
    float s, c;
    sincosf(ang, &s, &c);   // FIXED: sincosf(x, &sin, &cos)

    ((float2*)row)[lane] = make_float2(t1 * c - t2 * s, t1 * s + t2 * c);
}

// ---------------------------------------------------------------------------
// Sliding-window + global attention. One warp per (b, h, i) query.
// Keys: [0, gend) U [wlo, i],  wlo = max(0, i-256), gend = min(64, wlo).
// Scale 1/sqrt(64) folded into q.
// ---------------------------------------------------------------------------
__global__ __launch_bounds__(256) void attn_kernel() {
    const int gw   = blockIdx.x * 8 + (threadIdx.x >> 5);
    const int lane = threadIdx.x & 31;

    const int i = gw & (L_ - 1);
    const int h = (gw >> 11) & (NH - 1);
    const int b = gw >> 15;

    const float* qrow = g_q + ((size_t)(b * L_ + i)) * DIM_ + h * HD;
    const float q0 = qrow[lane]      * 0.125f;
    const float q1 = qrow[lane + 32] * 0.125f;

    const int hk = h >> 2;   // REP = 4
    const float* kb = g_k + (size_t)(b * L_) * KVD + hk * HD;
    const float* vb = g_v + (size_t)(b * L_) * KVD + hk * HD;

    float m = -1e30f, s = 0.0f, o0 = 0.0f, o1 = 0.0f;

    int wlo  = i - 256; if (wlo < 0) wlo = 0;
    int gend = wlo < 64 ? wlo : 64;

    #pragma unroll
    for (int seg = 0; seg < 2; seg++) {
        const int j0 = seg ? wlo : 0;
        const int j1 = seg ? (i + 1) : gend;
        for (int j = j0; j < j1; j++) {
            const float* kr = kb + (size_t)j * KVD;
            float p = q0 * kr[lane] + q1 * kr[lane + 32];
            #pragma unroll
            for (int off = 16; off > 0; off >>= 1)
                p += __shfl_xor_sync(0xffffffffu, p, off);

            float mn   = fmaxf(m, p);
            float corr = __expf(m - mn);
            float e    = __expf(p - mn);
            s = s * corr + e;
            const float* vr = vb + (size_t)j * KVD;
            o0 = o0 * corr + e * vr[lane];
            o1 = o1 * corr + e * vr[lane + 32];
            m = mn;
        }
    }

    const float inv = 1.0f / s;
    float* orow = g_ao + ((size_t)(b * L_ + i)) * DIM_ + h * HD;
    orow[lane]      = o0 * inv;
    orow[lane + 32] = o1 * inv;
}

// ---------------------------------------------------------------------------
extern "C" void kernel_launch(void* const* d_in, const int* in_sizes, int n_in,
                              void* d_out, int out_size) {
    const float* x  = (const float*)d_in[0];
    const float* wq = (const float*)d_in[1];
    const float* wk = (const float*)d_in[2];
    const float* wv = (const float*)d_in[3];
    const float* wo = (const float*)d_in[4];
    const float* gq = (const float*)d_in[5];
    const float* gk = (const float*)d_in[6];

    float *q, *k, *v, *ao;
    cudaGetSymbolAddress((void**)&q,  g_q);
    cudaGetSymbolAddress((void**)&k,  g_k);
    cudaGetSymbolAddress((void**)&v,  g_v);
    cudaGetSymbolAddress((void**)&ao, g_ao);

    // QKV projections
    sgemm64<<<dim3(DIM_ / 64, NTOK / 64), 256>>>(x, wq, q, NTOK, DIM_, DIM_);
    sgemm64<<<dim3(KVD  / 64, NTOK / 64), 256>>>(x, wk, k, NTOK, KVD,  DIM_);
    sgemm64<<<dim3(KVD  / 64, NTOK / 64), 256>>>(x, wv, v, NTOK, KVD,  DIM_);

    // RMSNorm + RoPE on q and k (in place)
    const int nrows = NTOK * NH + NTOK * NKV;   // 81920
    rmsrope_kernel<<<nrows / 8, 256>>>(gq, gk);

    // Attention
    attn_kernel<<<(NTOK * NH) / 8, 256>>>();

    // Output projection -> d_out
    sgemm64<<<dim3(DIM_ / 64, NTOK / 64), 256>>>(ao, wo, (float*)d_out, NTOK, DIM_, DIM_);
}

// round 5
// speedup vs baseline: 1.5871x; 1.5871x over previous
#include <cuda_runtime.h>
#include <math.h>

#define B_    2
#define L_    2048
#define DIM_  1024
#define NH    16
#define NKV   4
#define HD    64
#define KVD   (NKV*HD)      // 256
#define NTOK  (B_*L_)       // 4096

typedef unsigned long long u64;

// Scratch (no cudaMalloc allowed)
__device__ float g_q[NTOK*DIM_];     // 16 MB
__device__ float g_k[NTOK*KVD];      // 4 MB
__device__ float g_v[NTOK*KVD];      // 4 MB
__device__ float g_ao[NTOK*DIM_];    // 16 MB

// ---------------- packed f32x2 helpers (B300 FFMA2 path) -------------------
__device__ __forceinline__ u64 pk2(float x) {
    u64 r; asm("mov.b64 %0,{%1,%1};" : "=l"(r) : "f"(x)); return r;
}
__device__ __forceinline__ void fma2(u64 &d, u64 a, u64 b) {
    asm("fma.rn.f32x2 %0, %1, %2, %0;" : "+l"(d) : "l"(a), "l"(b));
}
__device__ __forceinline__ void mul2(u64 &d, u64 a) {
    asm("mul.rn.f32x2 %0, %0, %1;" : "+l"(d) : "l"(a));
}
__device__ __forceinline__ u64 add2(u64 a, u64 b) {
    u64 r; asm("add.rn.f32x2 %0, %1, %2;" : "=l"(r) : "l"(a), "l"(b)); return r;
}
__device__ __forceinline__ float2 up2(u64 a) {
    float2 f; asm("mov.b64 {%0,%1}, %2;" : "=f"(f.x), "=f"(f.y) : "l"(a)); return f;
}

// ---------------------------------------------------------------------------
// 128x128x16 fp32 GEMM body using FFMA2. Row-major A[M,K], B[K,N], C[M,N].
// 256 threads, 8x8 outputs/thread, register-staged tile prefetch.
// Requires M%128==0, N%128==0 (per sub-matrix), K%16==0.
// ---------------------------------------------------------------------------
__device__ __forceinline__ void gemm128_body(const float* __restrict__ A,
                                             const float* __restrict__ B,
                                             float* __restrict__ C,
                                             int m0, int n0, int N, int K) {
    __shared__ __align__(16) float As[16][132];
    __shared__ __align__(16) float Bs[16][128];

    const int tid = threadIdx.x;
    const int tx  = tid & 15;          // N sub-tile
    const int ty  = tid >> 4;          // M sub-tile

    const int arow = tid >> 2;             // 0..63 per 256-chunk
    const int acol = (tid & 3) << 2;       // 0,4,8,12
    const int brow = tid >> 5;             // 0..7 per chunk
    const int bcol = (tid & 31) << 2;      // 0..124

    u64 acc[8][4];
    #pragma unroll
    for (int i = 0; i < 8; i++)
        #pragma unroll
        for (int j = 0; j < 4; j++) acc[i][j] = 0ull;

    float4 ra[2], rb[2];
    const int NKB = K >> 4;

    // prologue: load tile 0
    #pragma unroll
    for (int l = 0; l < 2; l++) {
        ra[l] = *(const float4*)&A[(size_t)(m0 + arow + l * 64) * K + acol];
        rb[l] = *(const float4*)&B[(size_t)(brow + l * 8) * N + n0 + bcol];
    }
    #pragma unroll
    for (int l = 0; l < 2; l++) {
        As[acol + 0][arow + l * 64] = ra[l].x;
        As[acol + 1][arow + l * 64] = ra[l].y;
        As[acol + 2][arow + l * 64] = ra[l].z;
        As[acol + 3][arow + l * 64] = ra[l].w;
        *(float4*)&Bs[brow + l * 8][bcol] = rb[l];
    }
    __syncthreads();

    for (int kb = 0; kb < NKB; kb++) {
        if (kb + 1 < NKB) {
            const int k0 = (kb + 1) << 4;
            #pragma unroll
            for (int l = 0; l < 2; l++) {
                ra[l] = *(const float4*)&A[(size_t)(m0 + arow + l * 64) * K + k0 + acol];
                rb[l] = *(const float4*)&B[(size_t)(k0 + brow + l * 8) * N + n0 + bcol];
            }
        }
        #pragma unroll
        for (int kk = 0; kk < 16; kk++) {
            const ulonglong2* bp = (const ulonglong2*)&Bs[kk][tx << 3];
            ulonglong2 b01 = bp[0], b23 = bp[1];
            u64 bv[4] = {b01.x, b01.y, b23.x, b23.y};
            float4 a0 = *(const float4*)&As[kk][ty << 3];
            float4 a1 = *(const float4*)&As[kk][(ty << 3) + 4];
            float av[8] = {a0.x, a0.y, a0.z, a0.w, a1.x, a1.y, a1.z, a1.w};
            #pragma unroll
            for (int i = 0; i < 8; i++) {
                u64 ap = pk2(av[i]);
                #pragma unroll
                for (int j = 0; j < 4; j++) fma2(acc[i][j], ap, bv[j]);
            }
        }
        if (kb + 1 < NKB) {
            __syncthreads();
            #pragma unroll
            for (int l = 0; l < 2; l++) {
                As[acol + 0][arow + l * 64] = ra[l].x;
                As[acol + 1][arow + l * 64] = ra[l].y;
                As[acol + 2][arow + l * 64] = ra[l].z;
                As[acol + 3][arow + l * 64] = ra[l].w;
                *(float4*)&Bs[brow + l * 8][bcol] = rb[l];
            }
            __syncthreads();
        }
    }

    #pragma unroll
    for (int i = 0; i < 8; i++) {
        float* crow = &C[(size_t)(m0 + (ty << 3) + i) * N + n0 + (tx << 3)];
        ulonglong2 s0; s0.x = acc[i][0]; s0.y = acc[i][1];
        ulonglong2 s1; s1.x = acc[i][2]; s1.y = acc[i][3];
        ((ulonglong2*)crow)[0] = s0;
        ((ulonglong2*)crow)[1] = s1;
    }
}

__global__ __launch_bounds__(256) void sgemm128(const float* __restrict__ A,
                                                const float* __restrict__ B,
                                                float* __restrict__ C,
                                                int N, int K) {
    gemm128_body(A, B, C, blockIdx.y * 128, blockIdx.x * 128, N, K);
}

// Fused K+V projection: grid.x = 4; x<2 -> wk/g_k, else wv/g_v (N=256 each).
__global__ __launch_bounds__(256) void sgemm128_kv(const float* __restrict__ A,
                                                   const float* __restrict__ Bk,
                                                   const float* __restrict__ Bv,
                                                   float* __restrict__ Ck,
                                                   float* __restrict__ Cv,
                                                   int K) {
    const int bx = blockIdx.x;
    if (bx < 2) gemm128_body(A, Bk, Ck, blockIdx.y * 128, bx * 128, KVD, K);
    else        gemm128_body(A, Bv, Cv, blockIdx.y * 128, (bx - 2) * 128, KVD, K);
}

// ---------------------------------------------------------------------------
// Fused per-head RMSNorm + RoPE, in place on g_q / g_k. One warp per row.
// ---------------------------------------------------------------------------
__global__ __launch_bounds__(256) void rmsrope_kernel(const float* __restrict__ gq,
                                                      const float* __restrict__ gk) {
    const int gw   = blockIdx.x * 8 + (threadIdx.x >> 5);
    const int lane = threadIdx.x & 31;

    float* row;
    const float* g;
    int tok;
    if (gw < NTOK * NH) {
        tok = gw >> 4;
        int h = gw & 15;
        row = g_q + (size_t)tok * DIM_ + h * HD;
        g   = gq;
    } else {
        int r = gw - NTOK * NH;
        tok = r >> 2;
        int hk = r & 3;
        row = g_k + (size_t)tok * KVD + hk * HD;
        g   = gk;
    }
    const int pos = tok & (L_ - 1);

    float2 v = ((const float2*)row)[lane];
    float ss = v.x * v.x + v.y * v.y;
    #pragma unroll
    for (int off = 16; off > 0; off >>= 1)
        ss += __shfl_xor_sync(0xffffffffu, ss, off);
    float rn = rsqrtf(ss * (1.0f / 64.0f) + 1e-6f);

    float2 gg = ((const float2*)g)[lane];
    float t1 = v.x * rn * gg.x;
    float t2 = v.y * rn * gg.y;

    float inv_freq = exp2f((float)lane * (-13.287712379549449f / 32.0f));
    float ang = (float)pos * inv_freq;
    float s, c;
    sincosf(ang, &s, &c);

    ((float2*)row)[lane] = make_float2(t1 * c - t2 * s, t1 * s + t2 * c);
}

// ---------------------------------------------------------------------------
// Tiled sliding-window + global attention.
// Block = 128 threads: 2 q-heads x 64 queries; one thread = one q-row.
// grid: x=2 (head pair), y=32 (q tile), z=8 (b*NKV + hk).
// K/V staged in smem per 64-key chunk; q/o resident in f32x2 registers.
// ---------------------------------------------------------------------------
__global__ __launch_bounds__(128) void attn2_kernel() {
    __shared__ __align__(16) float Ks[64][64];
    __shared__ __align__(16) float Vs[64][64];

    const int tid = threadIdx.x;
    const int hr  = tid >> 6;            // 0/1
    const int qi  = tid & 63;
    const int t   = blockIdx.y;          // q tile
    const int hp  = blockIdx.x;          // head pair
    const int bz  = blockIdx.z;
    const int b   = bz >> 2;
    const int hk  = bz & 3;
    const int h   = hk * 4 + hp * 2 + hr;
    const int i   = t * 64 + qi;

    // q row -> registers (pre-scaled by 1/sqrt(64))
    u64 q2[32];
    {
        const ulonglong2* qp =
            (const ulonglong2*)(g_q + ((size_t)(b * L_ + i)) * DIM_ + h * HD);
        u64 sc = pk2(0.125f);
        #pragma unroll
        for (int c = 0; c < 16; c++) {
            ulonglong2 u = qp[c];
            q2[2 * c] = u.x; q2[2 * c + 1] = u.y;
            mul2(q2[2 * c], sc); mul2(q2[2 * c + 1], sc);
        }
    }

    u64 o2[32];
    #pragma unroll
    for (int c = 0; c < 32; c++) o2[c] = 0ull;
    float m = -1e30f, s = 0.0f;

    const float* kg = g_k + ((size_t)(b * L_)) * KVD + hk * HD;
    const float* vg = g_v + ((size_t)(b * L_)) * KVD + hk * HD;

    auto process_chunk = [&](int cc) {
        const int kb = cc * 64;
        __syncthreads();   // previous chunk fully consumed
        #pragma unroll
        for (int l = 0; l < 8; l++) {
            int idx = tid + l * 128;
            int r = idx >> 4, c = (idx & 15) << 2;
            *(float4*)&Ks[r][c] = *(const float4*)&kg[(size_t)(kb + r) * KVD + c];
            *(float4*)&Vs[r][c] = *(const float4*)&vg[(size_t)(kb + r) * KVD + c];
        }
        __syncthreads();

        #pragma unroll 1
        for (int jj = 0; jj < 64; jj++) {
            const int j = kb + jj;
            const ulonglong2* kv = (const ulonglong2*)Ks[jj];
            u64 d2[8];
            #pragma unroll
            for (int c = 0; c < 8; c++) d2[c] = 0ull;
            #pragma unroll
            for (int c = 0; c < 16; c++) {
                ulonglong2 l = kv[c];
                fma2(d2[(2 * c) & 7],     q2[2 * c],     l.x);
                fma2(d2[(2 * c + 1) & 7], q2[2 * c + 1], l.y);
            }
            u64 r0 = add2(add2(d2[0], d2[1]), add2(d2[2], d2[3]));
            u64 r1 = add2(add2(d2[4], d2[5]), add2(d2[6], d2[7]));
            float2 pf = up2(add2(r0, r1));
            float p = pf.x + pf.y;

            bool valid = (j <= i) && ((j >= i - 256) || (j < 64));
            float pv = valid ? p : -INFINITY;
            float mo = m;
            m = fmaxf(m, pv);
            float e = __expf(pv - m);
            u64 ep = pk2(e);
            const ulonglong2* vv = (const ulonglong2*)Vs[jj];

            if (__any_sync(0xffffffffu, m > mo)) {
                float corr = __expf(mo - m);
                s = s * corr + e;
                u64 cp = pk2(corr);
                #pragma unroll
                for (int c = 0; c < 16; c++) {
                    ulonglong2 l = vv[c];
                    mul2(o2[2 * c], cp);     fma2(o2[2 * c], ep, l.x);
                    mul2(o2[2 * c + 1], cp); fma2(o2[2 * c + 1], ep, l.y);
                }
            } else {
                s += e;
                #pragma unroll
                for (int c = 0; c < 16; c++) {
                    ulonglong2 l = vv[c];
                    fma2(o2[2 * c],     ep, l.x);
                    fma2(o2[2 * c + 1], ep, l.y);
                }
            }
        }
    };

    // chunks: global chunk 0, plus window chunks [max(0,t-4) .. t]
    if (t > 4) process_chunk(0);
    int c0 = t - 4; if (c0 < 0) c0 = 0;
    for (int cc = c0; cc <= t; cc++) process_chunk(cc);

    // normalize + store
    float inv = 1.0f / s;
    u64 ip = pk2(inv);
    ulonglong2* op = (ulonglong2*)(g_ao + ((size_t)(b * L_ + i)) * DIM_ + h * HD);
    #pragma unroll
    for (int c = 0; c < 16; c++) {
        mul2(o2[2 * c], ip); mul2(o2[2 * c + 1], ip);
        ulonglong2 u; u.x = o2[2 * c]; u.y = o2[2 * c + 1];
        op[c] = u;
    }
}

// ---------------------------------------------------------------------------
extern "C" void kernel_launch(void* const* d_in, const int* in_sizes, int n_in,
                              void* d_out, int out_size) {
    const float* x  = (const float*)d_in[0];
    const float* wq = (const float*)d_in[1];
    const float* wk = (const float*)d_in[2];
    const float* wv = (const float*)d_in[3];
    const float* wo = (const float*)d_in[4];
    const float* gq = (const float*)d_in[5];
    const float* gk = (const float*)d_in[6];

    float *q, *k, *v, *ao;
    cudaGetSymbolAddress((void**)&q,  g_q);
    cudaGetSymbolAddress((void**)&k,  g_k);
    cudaGetSymbolAddress((void**)&v,  g_v);
    cudaGetSymbolAddress((void**)&ao, g_ao);

    // Q projection + fused K/V projections
    sgemm128<<<dim3(DIM_ / 128, NTOK / 128), 256>>>(x, wq, q, DIM_, DIM_);
    sgemm128_kv<<<dim3(4, NTOK / 128), 256>>>(x, wk, wv, k, v, DIM_);

    // RMSNorm + RoPE on q and k (in place)
    const int nrows = NTOK * NH + NTOK * NKV;   // 81920
    rmsrope_kernel<<<nrows / 8, 256>>>(gq, gk);

    // Attention
    attn2_kernel<<<dim3(2, 32, 8), 128>>>();

    // Output projection -> d_out
    sgemm128<<<dim3(DIM_ / 128, NTOK / 128), 256>>>(ao, wo, (float*)d_out, DIM_, DIM_);
}